// round 10
// baseline (speedup 1.0000x reference)
#include <cuda_runtime.h>
#include <cstdint>

#define T_DIM 8192
#define H_DIM 2048
#define D_DIM 1024
#define CHUNKS 64
#define CLEN 128            // T_DIM / CHUNKS

#define BM 128
#define BN 128
#define BK 32
#define SSTRIDE 36          // padded smem row stride (floats): bank-conflict-free frags
#define KT (D_DIM / BK)     // 32 k-tiles
#define SMEM_BYTES (2 * 2 * BM * SSTRIDE * 4)   // 2 operands * 2 stages * 128*36 floats = 73728 B

// ---------------- device scratch (static allocations are the sanctioned path) ----
__device__ float g_V1[(size_t)T_DIM * H_DIM];   // gamma * (x @ B1^T)
__device__ float g_V2[(size_t)T_DIM * H_DIM];   // gamma * (x @ B2^T)
__device__ float g_a[H_DIM], g_b[H_DIM], g_gamma[H_DIM];
__device__ float g_aL[H_DIM], g_bL[H_DIM];      // c^CLEN
__device__ float g_E1[CHUNKS * H_DIM], g_E2[CHUNKS * H_DIM];  // chunk-local scan ends
__device__ float g_P1[CHUNKS * H_DIM], g_P2[CHUNKS * H_DIM];  // chunk-start states

// ---------------- per-head parameters -------------------------------------------
__global__ void param_kernel(const float* __restrict__ lamda,
                             const float* __restrict__ theta) {
    int h = blockIdx.x * blockDim.x + threadIdx.x;
    if (h >= H_DIM) return;
    float y = expf(-expf(lamda[h]));
    float z = expf(theta[h]);
    float gamma = sqrtf(fmaxf(1.0f - y * y, 0.0f));
    float a = y * cosf(z);
    float b = y * sinf(z);
    g_a[h] = a; g_b[h] = b; g_gamma[h] = gamma;
    // c^CLEN by repeated complex multiply (|c| < 1, numerically stable)
    float ar = 1.0f, ai = 0.0f;
    #pragma unroll 8
    for (int i = 0; i < CLEN; i++) {
        float nr = ar * a - ai * b;
        float ni = ar * b + ai * a;
        ar = nr; ai = ni;
    }
    g_aL[h] = ar; g_bL[h] = ai;
}

// ---------------- tf32 GEMM: V = gamma .* (x @ B^T) ------------------------------
__device__ __forceinline__ uint32_t f2tf32(float x) {
    uint32_t r;
    asm("cvt.rna.tf32.f32 %0, %1;" : "=r"(r) : "f"(x));
    return r;
}

__global__ __launch_bounds__(256, 1)
void gemm_kernel(const float* __restrict__ X,
                 const float* __restrict__ B1,
                 const float* __restrict__ B2) {
    extern __shared__ float smem[];
    float* As = smem;                           // [2][BM*SSTRIDE]
    float* Bs = smem + 2 * BM * SSTRIDE;        // [2][BN*SSTRIDE]
    const float* Bmat = (blockIdx.z == 0) ? B1 : B2;
    float* V = (blockIdx.z == 0) ? g_V1 : g_V2;

    const int tid = threadIdx.x;
    const int warp = tid >> 5, lane = tid & 31;
    const int wm = warp >> 2, wn = warp & 3;    // 2 x 4 warp grid, warp tile 64x32
    const int m0 = blockIdx.x * BM;
    const int n0 = blockIdx.y * BN;

    float acc[4][4][4];
    #pragma unroll
    for (int i = 0; i < 4; i++)
        #pragma unroll
        for (int j = 0; j < 4; j++)
            #pragma unroll
            for (int k = 0; k < 4; k++) acc[i][j][k] = 0.0f;

    auto issue = [&](int stage, int kt) {
        const int k0 = kt * BK;
        #pragma unroll
        for (int i = 0; i < 4; i++) {
            int c = tid + i * 256;              // 1024 16B-chunks per operand tile
            int row = c >> 3, cc = c & 7;
            const float* gA = X + (size_t)(m0 + row) * D_DIM + k0 + cc * 4;
            uint32_t dA = (uint32_t)__cvta_generic_to_shared(
                As + stage * BM * SSTRIDE + row * SSTRIDE + cc * 4);
            asm volatile("cp.async.cg.shared.global [%0], [%1], 16;" :: "r"(dA), "l"(gA));
            const float* gB = Bmat + (size_t)(n0 + row) * D_DIM + k0 + cc * 4;
            uint32_t dB = (uint32_t)__cvta_generic_to_shared(
                Bs + stage * BM * SSTRIDE + row * SSTRIDE + cc * 4);
            asm volatile("cp.async.cg.shared.global [%0], [%1], 16;" :: "r"(dB), "l"(gB));
        }
        asm volatile("cp.async.commit_group;");
    };

    issue(0, 0);
    for (int kt = 0; kt < KT; kt++) {
        if (kt + 1 < KT) {
            issue((kt + 1) & 1, kt + 1);
            asm volatile("cp.async.wait_group 1;");
        } else {
            asm volatile("cp.async.wait_group 0;");
        }
        __syncthreads();
        const float* Asb = As + (kt & 1) * BM * SSTRIDE;
        const float* Bsb = Bs + (kt & 1) * BM * SSTRIDE;
        #pragma unroll
        for (int ks = 0; ks < 4; ks++) {
            const int kb = ks * 8;
            uint32_t af[4][4];
            #pragma unroll
            for (int mi = 0; mi < 4; mi++) {
                int r = wm * 64 + mi * 16 + (lane >> 2);
                int cidx = kb + (lane & 3);
                af[mi][0] = f2tf32(Asb[r * SSTRIDE + cidx]);
                af[mi][1] = f2tf32(Asb[(r + 8) * SSTRIDE + cidx]);
                af[mi][2] = f2tf32(Asb[r * SSTRIDE + cidx + 4]);
                af[mi][3] = f2tf32(Asb[(r + 8) * SSTRIDE + cidx + 4]);
            }
            uint32_t bfr[4][2];
            #pragma unroll
            for (int ni = 0; ni < 4; ni++) {
                int n = wn * 32 + ni * 8 + (lane >> 2);
                int kk = kb + (lane & 3);
                bfr[ni][0] = f2tf32(Bsb[n * SSTRIDE + kk]);
                bfr[ni][1] = f2tf32(Bsb[n * SSTRIDE + kk + 4]);
            }
            #pragma unroll
            for (int mi = 0; mi < 4; mi++)
                #pragma unroll
                for (int ni = 0; ni < 4; ni++) {
                    asm volatile(
                        "mma.sync.aligned.m16n8k8.row.col.f32.tf32.tf32.f32 "
                        "{%0,%1,%2,%3}, {%4,%5,%6,%7}, {%8,%9}, {%0,%1,%2,%3};"
                        : "+f"(acc[mi][ni][0]), "+f"(acc[mi][ni][1]),
                          "+f"(acc[mi][ni][2]), "+f"(acc[mi][ni][3])
                        : "r"(af[mi][0]), "r"(af[mi][1]), "r"(af[mi][2]), "r"(af[mi][3]),
                          "r"(bfr[ni][0]), "r"(bfr[ni][1]));
                }
        }
        __syncthreads();
    }

    // epilogue: scale by gamma[h], store fp32
    #pragma unroll
    for (int mi = 0; mi < 4; mi++) {
        #pragma unroll
        for (int ni = 0; ni < 4; ni++) {
            int r = m0 + wm * 64 + mi * 16 + (lane >> 2);
            int h = n0 + wn * 32 + ni * 8 + 2 * (lane & 3);
            float gm0 = g_gamma[h], gm1 = g_gamma[h + 1];
            float2 v0 = make_float2(acc[mi][ni][0] * gm0, acc[mi][ni][1] * gm1);
            float2 v1 = make_float2(acc[mi][ni][2] * gm0, acc[mi][ni][3] * gm1);
            *(float2*)(V + (size_t)r * H_DIM + h) = v0;
            *(float2*)(V + (size_t)(r + 8) * H_DIM + h) = v1;
        }
    }
}

// ---------------- chunked scan --------------------------------------------------
// Phase 1: per-(head,chunk) local scan from zero state; record chunk-end state.
__global__ void scan_local_kernel() {
    int tid = blockIdx.x * blockDim.x + threadIdx.x;   // H*CHUNKS threads
    int h = tid & (H_DIM - 1);
    int chunk = tid >> 11;                             // H_DIM = 2048 = 2^11
    float a = g_a[h], b = g_b[h];
    float s1 = 0.0f, s2 = 0.0f;
    int base = chunk * CLEN * H_DIM + h;
    #pragma unroll 4
    for (int k = 0; k < CLEN; k++) {
        float v1 = g_V1[base + k * H_DIM];
        float v2 = g_V2[base + k * H_DIM];
        float n1 = fmaf(a, s1, fmaf(-b, s2, v1));
        float n2 = fmaf(a, s2, fmaf(b, s1, v2));
        s1 = n1; s2 = n2;
    }
    g_E1[chunk * H_DIM + h] = s1;
    g_E2[chunk * H_DIM + h] = s2;
}

// Phase 2: per-head prefix over chunks: P[j] = state just before chunk j starts.
__global__ void scan_prefix_kernel() {
    int h = blockIdx.x * blockDim.x + threadIdx.x;
    if (h >= H_DIM) return;
    float aL = g_aL[h], bL = g_bL[h];
    float p1 = 0.0f, p2 = 0.0f;
    for (int j = 0; j < CHUNKS; j++) {
        g_P1[j * H_DIM + h] = p1;
        g_P2[j * H_DIM + h] = p2;
        float e1 = g_E1[j * H_DIM + h];
        float e2 = g_E2[j * H_DIM + h];
        float n1 = fmaf(aL, p1, fmaf(-bL, p2, e1));
        float n2 = fmaf(aL, p2, fmaf(bL, p1, e2));
        p1 = n1; p2 = n2;
    }
}

// Phase 3: re-run local scans seeded with chunk-start states, write output [T, 2H].
__global__ void scan_final_kernel(float* __restrict__ out) {
    int tid = blockIdx.x * blockDim.x + threadIdx.x;
    int h = tid & (H_DIM - 1);
    int chunk = tid >> 11;
    float a = g_a[h], b = g_b[h];
    float s1 = g_P1[chunk * H_DIM + h];
    float s2 = g_P2[chunk * H_DIM + h];
    int base = chunk * CLEN * H_DIM + h;
    int obase = chunk * CLEN * 2 * H_DIM + h;
    #pragma unroll 4
    for (int k = 0; k < CLEN; k++) {
        float v1 = g_V1[base + k * H_DIM];
        float v2 = g_V2[base + k * H_DIM];
        float n1 = fmaf(a, s1, fmaf(-b, s2, v1));
        float n2 = fmaf(a, s2, fmaf(b, s1, v2));
        s1 = n1; s2 = n2;
        out[obase + k * 2 * H_DIM] = s1;
        out[obase + k * 2 * H_DIM + H_DIM] = s2;
    }
}

// ---------------- launcher ------------------------------------------------------
extern "C" void kernel_launch(void* const* d_in, const int* in_sizes, int n_in,
                              void* d_out, int out_size) {
    const float* x     = (const float*)d_in[0];   // [T, D]
    const float* lamda = (const float*)d_in[1];   // [H]
    const float* theta = (const float*)d_in[2];   // [H]
    const float* B1    = (const float*)d_in[3];   // [H, D]
    const float* B2    = (const float*)d_in[4];   // [H, D]
    float* out = (float*)d_out;                   // [T, 2H]

    cudaFuncSetAttribute(gemm_kernel,
                         cudaFuncAttributeMaxDynamicSharedMemorySize, SMEM_BYTES);

    param_kernel<<<(H_DIM + 255) / 256, 256>>>(lamda, theta);

    dim3 grid(T_DIM / BM, H_DIM / BN, 2);
    gemm_kernel<<<grid, 256, SMEM_BYTES>>>(x, B1, B2);

    scan_local_kernel<<<(H_DIM * CHUNKS) / 256, 256>>>();
    scan_prefix_kernel<<<(H_DIM + 255) / 256, 256>>>();
    scan_final_kernel<<<(H_DIM * CHUNKS) / 256, 256>>>(out);
}